// round 1
// baseline (speedup 1.0000x reference)
#include <cuda_runtime.h>

// DotInteraction: B=16384 rows. T = [dense(1x128); embs(26x128)] per row.
// out[b, p] = dot(T[i], T[j]) for strict upper triangle pairs p=(i,j), j>i,
// in row-major triu order (matches jnp.triu_indices(27, k=1)).

constexpr int Bt     = 16384;
constexpr int NE     = 26;
constexpr int D      = 128;
constexpr int N      = 27;      // 1 + NE
constexpr int NPAIR  = N * (N - 1) / 2;  // 351
constexpr int NTHR   = 256;
constexpr int NWARP  = NTHR / 32;

__global__ void __launch_bounds__(NTHR, 8)
dot_interaction_kernel(const float* __restrict__ dense,
                       const float* __restrict__ embs,
                       float* __restrict__ out)
{
    __shared__ float T[N][D];       // 13824 B
    __shared__ float R[NPAIR];      // 1404 B

    const int row  = blockIdx.x;
    const int tid  = threadIdx.x;
    const int warp = tid >> 5;
    const int lane = tid & 31;

    // ---- Load phase: coalesced float4 streams ----
    // T[0] = dense row (128 floats = 32 float4)
    // T[1..26] = embs row (3328 floats = 832 float4), contiguous in gmem
    const float4* d4 = reinterpret_cast<const float4*>(dense + (size_t)row * D);
    const float4* e4 = reinterpret_cast<const float4*>(embs + (size_t)row * NE * D);
    float4* T4 = reinterpret_cast<float4*>(&T[0][0]);

    if (tid < 32) T4[tid] = d4[tid];
    #pragma unroll
    for (int i = 0; i < (NE * D / 4 + NTHR - 1) / NTHR; i++) {
        int idx = tid + i * NTHR;
        if (idx < NE * D / 4) T4[32 + idx] = e4[idx];
    }
    __syncthreads();

    // ---- Compute phase: one warp per pair, round-robin over 8 warps ----
    int p = 0;
    for (int i = 0; i < N; i++) {
        for (int j = i + 1; j < N; j++) {
            if ((p & (NWARP - 1)) == warp) {
                // lane covers 4 consecutive dims; 32 lanes cover D=128.
                // Addresses stride 16B -> 4 conflict-free 128B phases.
                float4 a = reinterpret_cast<const float4*>(T[i])[lane];
                float4 b = reinterpret_cast<const float4*>(T[j])[lane];
                float s = a.x * b.x + a.y * b.y + a.z * b.z + a.w * b.w;
                #pragma unroll
                for (int o = 16; o > 0; o >>= 1)
                    s += __shfl_xor_sync(0xFFFFFFFFu, s, o);
                if (lane == 0) R[p] = s;
            }
            p++;
        }
    }
    __syncthreads();

    // ---- Write phase: coalesced ----
    float* orow = out + (size_t)row * NPAIR;
    #pragma unroll
    for (int i = 0; i < (NPAIR + NTHR - 1) / NTHR; i++) {
        int idx = tid + i * NTHR;
        if (idx < NPAIR) orow[idx] = R[idx];
    }
}

extern "C" void kernel_launch(void* const* d_in, const int* in_sizes, int n_in,
                              void* d_out, int out_size)
{
    const float* dense = (const float*)d_in[0];
    const float* embs  = (const float*)d_in[1];
    float* out = (float*)d_out;
    dot_interaction_kernel<<<Bt, NTHR>>>(dense, embs, out);
}

// round 6
// speedup vs baseline: 4.7708x; 4.7708x over previous
#include <cuda_runtime.h>

// DLRM dot-interaction: B=16384, T = [dense(1x128); embs(26x128)], out = triu(T·T^T, k=1).
// One warp per sample. Each of 28 lanes owns a 4x4 tile of the 28x28 (padded) Z,
// with tile rows strided by 7 ({t, t+7, t+14, t+21}) so shared-memory loads are
// conflict-free with a 132-float row stride. Z is symmetric, so tiles producing
// (i>j) entries store to the sorted triu index.

constexpr int Bt      = 16384;
constexpr int NE      = 26;
constexpr int D       = 128;
constexpr int N       = 27;
constexpr int NPAIR   = N * (N - 1) / 2;   // 351
constexpr int NROW    = 28;                // padded rows (row 27 = zeros)
constexpr int STRIDE4 = 33;                // float4 per smem row (132 floats)
constexpr int SPC     = 2;                 // samples (warps) per CTA
constexpr int NTHR    = SPC * 32;          // 64

__global__ void __launch_bounds__(NTHR)
dot_interaction_kernel(const float* __restrict__ dense,
                       const float* __restrict__ embs,
                       float* __restrict__ out)
{
    __shared__ float4 S[SPC][NROW * STRIDE4];   // 2 * 28 * 33 * 16 = 29568 B

    const int warp = threadIdx.x >> 5;
    const int lane = threadIdx.x & 31;
    const int sample = blockIdx.x * SPC + warp;

    float4* Ss = S[warp];

    // ---- Load phase (warp-private, fully coalesced 512B bursts) ----
    const float4* d4 = reinterpret_cast<const float4*>(dense + (size_t)sample * D);
    const float4* e4 = reinterpret_cast<const float4*>(embs + (size_t)sample * NE * D);

    Ss[0 * STRIDE4 + lane] = d4[lane];          // row 0 = dense
    #pragma unroll
    for (int r = 0; r < NE; r++)                // rows 1..26 = embs
        Ss[(r + 1) * STRIDE4 + lane] = e4[r * 32 + lane];
    Ss[27 * STRIDE4 + lane] = make_float4(0.f, 0.f, 0.f, 0.f);  // pad row
    __syncwarp();

    // ---- Tile coords: lane l (0..27) -> (ti, tj), ti<=tj, row-major over the
    // 7x7 upper triangle (row lengths 7,6,5,4,3,2,1). The `ti == r` guard makes
    // the sequential row-consumption scan monotone (cannot re-trigger after the
    // first failure — the bug that broke R4).
    const int li = min(lane, 27);
    int ti = 0;
    int rem = li;
    #pragma unroll
    for (int r = 0; r < 6; r++) {
        if (ti == r && rem >= 7 - r) { rem -= 7 - r; ti = r + 1; }
    }
    const int tj = ti + rem;

    const float4* ap = Ss + ti * STRIDE4;
    const float4* bp = Ss + tj * STRIDE4;

    // ---- Compute phase: 4x4 register tile per lane, rows strided by 7 ----
    float acc[4][4];
    #pragma unroll
    for (int r = 0; r < 4; r++)
        #pragma unroll
        for (int c = 0; c < 4; c++) acc[r][c] = 0.f;

    #pragma unroll 4
    for (int k = 0; k < D / 4; k++) {
        float4 a[4], b[4];
        #pragma unroll
        for (int r = 0; r < 4; r++) a[r] = ap[(7 * r) * STRIDE4 + k];
        #pragma unroll
        for (int c = 0; c < 4; c++) b[c] = bp[(7 * c) * STRIDE4 + k];
        #pragma unroll
        for (int r = 0; r < 4; r++)
            #pragma unroll
            for (int c = 0; c < 4; c++) {
                float s = acc[r][c];
                s = fmaf(a[r].x, b[c].x, s);
                s = fmaf(a[r].y, b[c].y, s);
                s = fmaf(a[r].z, b[c].z, s);
                s = fmaf(a[r].w, b[c].w, s);
                acc[r][c] = s;
            }
    }

    // ---- Epilogue: store valid pairs to sorted triu index ----
    if (lane < 28) {
        float* orow = out + (size_t)sample * NPAIR;
        #pragma unroll
        for (int r = 0; r < 4; r++) {
            const int i = ti + 7 * r;
            #pragma unroll
            for (int c = 0; c < 4; c++) {
                const int j = tj + 7 * c;
                if (i != j) {
                    const int ii = min(i, j);
                    const int jj = max(i, j);
                    if (jj < N) {
                        const int p = ii * (2 * N - 1 - ii) / 2 + (jj - ii - 1);
                        orow[p] = acc[r][c];
                    }
                }
            }
        }
    }
}

extern "C" void kernel_launch(void* const* d_in, const int* in_sizes, int n_in,
                              void* d_out, int out_size)
{
    const float* dense = (const float*)d_in[0];
    const float* embs  = (const float*)d_in[1];
    float* out = (float*)d_out;
    const int grid = Bt / SPC;                  // 8192, Bt divisible by SPC
    dot_interaction_kernel<<<grid, NTHR>>>(dense, embs, out);
}

// round 7
// speedup vs baseline: 5.7711x; 1.2097x over previous
#include <cuda_runtime.h>

// DLRM dot-interaction: B=16384, T = [dense(1x128); embs(26x128)], out = triu(T·T^T, k=1).
// TWO warps per sample (split-k over 64 dims each). Each of 28 lanes owns a 4x4
// tile of the 28x28 (padded) Z with tile rows strided by 7, conflict-free against
// the 132-float smem row stride. After compute, the k-upper warp dumps its partial
// tiles into the (dead) T smem and the k-lower warp reduces + stores.

constexpr int Bt      = 16384;
constexpr int NE      = 26;
constexpr int D       = 128;
constexpr int N       = 27;
constexpr int NPAIR   = N * (N - 1) / 2;   // 351
constexpr int NROW    = 28;                // padded rows (row 27 = zeros)
constexpr int STRIDE4 = 33;                // float4 per smem row (132 floats)
constexpr int SPC     = 2;                 // samples per CTA
constexpr int WPS     = 2;                 // warps per sample (split-k)
constexpr int NTHR    = SPC * WPS * 32;    // 128

__global__ void __launch_bounds__(NTHR)
dot_interaction_kernel(const float* __restrict__ dense,
                       const float* __restrict__ embs,
                       float* __restrict__ out)
{
    __shared__ float4 S[SPC][NROW * STRIDE4];   // 2 * 28 * 33 * 16 = 29568 B

    const int warp  = threadIdx.x >> 5;
    const int lane  = threadIdx.x & 31;
    const int sloc  = warp >> 1;               // sample within CTA (0..1)
    const int kw    = warp & 1;                // k-half (0: dims 0-63, 1: 64-127)
    const int sample = blockIdx.x * SPC + sloc;

    float4* Ss = S[sloc];
    float*  Sf = reinterpret_cast<float*>(Ss); // reused as reduction buffer later

    // ---- Load phase: 64 threads (both warps of the sample) load its 27 rows ----
    {
        const int t = (kw << 5) | lane;        // 0..63 within the sample pair
        const float4* d4 = reinterpret_cast<const float4*>(dense + (size_t)sample * D);
        const float4* e4 = reinterpret_cast<const float4*>(embs + (size_t)sample * NE * D);
        if (t < 32) Ss[t] = d4[t];             // row 0 = dense
        else        Ss[27 * STRIDE4 + (t - 32)] = make_float4(0.f, 0.f, 0.f, 0.f); // pad row
        #pragma unroll
        for (int i = 0; i < (NE * 32) / 64; i++) {   // 832 float4 over 64 threads, 13 iters
            const int idx = t + i * 64;
            const int row = idx >> 5, col = idx & 31;
            Ss[(row + 1) * STRIDE4 + col] = e4[idx];
        }
    }
    __syncthreads();

    // ---- Tile coords: lane l (0..27) -> (ti, tj), ti<=tj, row-major over the
    // 7x7 upper triangle (row lengths 7,6,5,4,3,2,1). Monotone scan (ti==r guard).
    const int li = min(lane, 27);
    int ti = 0;
    int rem = li;
    #pragma unroll
    for (int r = 0; r < 6; r++) {
        if (ti == r && rem >= 7 - r) { rem -= 7 - r; ti = r + 1; }
    }
    const int tj = ti + rem;

    const int kbase = kw * (D / 8);            // 16 float4 per k-half
    const float4* ap = Ss + ti * STRIDE4 + kbase;
    const float4* bp = Ss + tj * STRIDE4 + kbase;

    // ---- Compute phase: 4x4 register tile per lane over this warp's k-half ----
    float acc[4][4];
    #pragma unroll
    for (int r = 0; r < 4; r++)
        #pragma unroll
        for (int c = 0; c < 4; c++) acc[r][c] = 0.f;

    #pragma unroll 4
    for (int k = 0; k < D / 8; k++) {          // 16 steps of float4
        float4 a[4], b[4];
        #pragma unroll
        for (int r = 0; r < 4; r++) a[r] = ap[(7 * r) * STRIDE4 + k];
        #pragma unroll
        for (int c = 0; c < 4; c++) b[c] = bp[(7 * c) * STRIDE4 + k];
        #pragma unroll
        for (int r = 0; r < 4; r++)
            #pragma unroll
            for (int c = 0; c < 4; c++) {
                float s = acc[r][c];
                s = fmaf(a[r].x, b[c].x, s);
                s = fmaf(a[r].y, b[c].y, s);
                s = fmaf(a[r].z, b[c].z, s);
                s = fmaf(a[r].w, b[c].w, s);
                acc[r][c] = s;
            }
    }

    // ---- Cross-warp reduction: reuse the (now dead) tile smem ----
    __syncthreads();                            // all warps done reading T
    if (kw == 1) {
        #pragma unroll
        for (int e = 0; e < 16; e++)
            Sf[e * 32 + lane] = acc[e >> 2][e & 3];   // [e][lane]: conflict-free
    }
    __syncthreads();

    // ---- Epilogue: k-lower warp adds partner's partials and stores triu ----
    if (kw == 0 && lane < 28) {
        float* orow = out + (size_t)sample * NPAIR;
        #pragma unroll
        for (int r = 0; r < 4; r++) {
            const int i = ti + 7 * r;
            #pragma unroll
            for (int c = 0; c < 4; c++) {
                const int j = tj + 7 * c;
                const float v = acc[r][c] + Sf[(r * 4 + c) * 32 + lane];
                if (i != j) {
                    const int ii = min(i, j);
                    const int jj = max(i, j);
                    if (jj < N) {
                        const int p = ii * (2 * N - 1 - ii) / 2 + (jj - ii - 1);
                        orow[p] = v;
                    }
                }
            }
        }
    }
}

extern "C" void kernel_launch(void* const* d_in, const int* in_sizes, int n_in,
                              void* d_out, int out_size)
{
    const float* dense = (const float*)d_in[0];
    const float* embs  = (const float*)d_in[1];
    float* out = (float*)d_out;
    const int grid = Bt / SPC;                  // 8192
    dot_interaction_kernel<<<grid, NTHR>>>(dense, embs, out);
}

// round 8
// speedup vs baseline: 6.2039x; 1.0750x over previous
#include <cuda_runtime.h>
#include <cstdint>

// DLRM dot-interaction via TF32 tensor cores (3xTF32 for fp32-grade accuracy).
// One sample per 64-thread CTA (2 warps, split-k: 64 dims each).
// T padded to 32x128 in smem (rows 27..31 zero). Z = T*T^T computed as
// 2 mtiles x 4 ntiles x 8 ktiles of mma.m16n8k8.tf32 per warp, 3 mma per
// position: a_hi*b_hi + a_hi*b_lo + a_lo*b_hi (mask split, residual ~2^-20).

constexpr int Bt      = 16384;
constexpr int NE      = 26;
constexpr int D       = 128;
constexpr int N       = 27;
constexpr int NPAIR   = N * (N - 1) / 2;   // 351
constexpr int NROWS   = 32;                // padded for m16 tiles
constexpr int STRIDEF = 132;               // floats per smem row (33 float4)
constexpr int NTHR    = 64;

__device__ __forceinline__ void mma_tf32(float* c, const uint32_t* a, const uint32_t* b)
{
    asm volatile(
        "mma.sync.aligned.m16n8k8.row.col.f32.tf32.tf32.f32 "
        "{%0,%1,%2,%3}, {%4,%5,%6,%7}, {%8,%9}, {%0,%1,%2,%3};"
        : "+f"(c[0]), "+f"(c[1]), "+f"(c[2]), "+f"(c[3])
        : "r"(a[0]), "r"(a[1]), "r"(a[2]), "r"(a[3]), "r"(b[0]), "r"(b[1]));
}

__device__ __forceinline__ void split_tf32(float x, uint32_t& hi, uint32_t& lo)
{
    uint32_t h = __float_as_uint(x) & 0xFFFFE000u;   // top 10 explicit mantissa bits
    hi = h;
    lo = __float_as_uint(x - __uint_as_float(h));    // exact residual in fp32
}

__global__ void __launch_bounds__(NTHR)
dot_interaction_kernel(const float* __restrict__ dense,
                       const float* __restrict__ embs,
                       float* __restrict__ out)
{
    __shared__ float S[NROWS * STRIDEF];             // 16896 B

    const int tid  = threadIdx.x;
    const int kw   = tid >> 5;                       // k-half: 0 or 1
    const int lane = tid & 31;
    const int g    = lane >> 2;                      // groupID
    const int t4   = lane & 3;                       // thread-in-group
    const int sample = blockIdx.x;

    // ---- Load phase: 64 threads stage T (32x128, rows 27..31 zero) ----
    float4* S4 = reinterpret_cast<float4*>(S);
    const float4* d4 = reinterpret_cast<const float4*>(dense + (size_t)sample * D);
    const float4* e4 = reinterpret_cast<const float4*>(embs + (size_t)sample * NE * D);

    if (tid < 32) S4[tid] = d4[tid];                 // row 0 = dense (32 float4)
    #pragma unroll
    for (int i = tid; i < NE * 32; i += NTHR) {      // rows 1..26 = embs (832 f4)
        const int row = i >> 5, col = i & 31;
        S4[(row + 1) * 33 + col] = e4[i];
    }
    #pragma unroll
    for (int i = tid; i < 5 * 33; i += NTHR)         // rows 27..31 = zero (165 f4)
        S4[27 * 33 + i] = make_float4(0.f, 0.f, 0.f, 0.f);
    __syncthreads();

    // ---- Compute: this warp covers k dims [kw*64, kw*64+64) = 8 ktiles ----
    float acc[8][4];                                 // [mt*4+nt][c]
    #pragma unroll
    for (int e = 0; e < 8; e++)
        #pragma unroll
        for (int c = 0; c < 4; c++) acc[e][c] = 0.f;

    const int kbase = kw * 64;

    #pragma unroll
    for (int kt = 0; kt < 8; kt++) {
        const int k0 = kbase + kt * 8;

        // A fragments (rows m, cols k): a0=(m0,k+t4) a1=(m0+8,..) a2=(m0,k+t4+4) a3=(m0+8,..)
        uint32_t ah[2][4], al[2][4];
        #pragma unroll
        for (int mt = 0; mt < 2; mt++) {
            const int m0 = mt * 16 + g;
            split_tf32(S[ m0      * STRIDEF + k0 + t4    ], ah[mt][0], al[mt][0]);
            split_tf32(S[(m0 + 8) * STRIDEF + k0 + t4    ], ah[mt][1], al[mt][1]);
            split_tf32(S[ m0      * STRIDEF + k0 + t4 + 4], ah[mt][2], al[mt][2]);
            split_tf32(S[(m0 + 8) * STRIDEF + k0 + t4 + 4], ah[mt][3], al[mt][3]);
        }
        // B fragments (col-major 8k x 8n): b0=(k+t4, n), b1=(k+t4+4, n); B[k][n]=T[n][k]
        uint32_t bh[4][2], bl[4][2];
        #pragma unroll
        for (int nt = 0; nt < 4; nt++) {
            const int n = nt * 8 + g;
            split_tf32(S[n * STRIDEF + k0 + t4    ], bh[nt][0], bl[nt][0]);
            split_tf32(S[n * STRIDEF + k0 + t4 + 4], bh[nt][1], bl[nt][1]);
        }
        // 3xTF32: small terms first, then hi*hi
        #pragma unroll
        for (int mt = 0; mt < 2; mt++)
            #pragma unroll
            for (int nt = 0; nt < 4; nt++) {
                float* c = acc[mt * 4 + nt];
                mma_tf32(c, al[mt], bh[nt]);
                mma_tf32(c, ah[mt], bl[nt]);
                mma_tf32(c, ah[mt], bh[nt]);
            }
    }

    // ---- Cross-warp reduction via dead tile smem (4 KB at base of S) ----
    __syncthreads();                                 // everyone done reading T
    if (kw == 1) {
        #pragma unroll
        for (int e = 0; e < 8; e++)
            #pragma unroll
            for (int c = 0; c < 4; c++)
                S[(e * 4 + c) * 32 + lane] = acc[e][c];
    }
    __syncthreads();

    // ---- Epilogue: warp 0 adds partner partials, scatters strict-upper triu ----
    if (kw == 0) {
        float* orow = out + (size_t)sample * NPAIR;
        #pragma unroll
        for (int mt = 0; mt < 2; mt++)
            #pragma unroll
            for (int nt = 0; nt < 4; nt++)
                #pragma unroll
                for (int c = 0; c < 4; c++) {
                    const int e = mt * 4 + nt;
                    const float v = acc[e][c] + S[(e * 4 + c) * 32 + lane];
                    const int i = mt * 16 + g + ((c & 2) ? 8 : 0);
                    const int j = nt * 8 + 2 * t4 + (c & 1);
                    if (i < j && j < N)
                        orow[i * (2 * N - 1 - i) / 2 + (j - i - 1)] = v;
                }
    }
}

extern "C" void kernel_launch(void* const* d_in, const int* in_sizes, int n_in,
                              void* d_out, int out_size)
{
    const float* dense = (const float*)d_in[0];
    const float* embs  = (const float*)d_in[1];
    float* out = (float*)d_out;
    dot_interaction_kernel<<<Bt, NTHR>>>(dense, embs, out);
}

// round 9
// speedup vs baseline: 7.0902x; 1.1429x over previous
#include <cuda_runtime.h>
#include <cstdint>

// DLRM dot-interaction via TF32 tensor cores (3xTF32 for fp32-grade accuracy).
// One sample per 64-thread CTA (2 warps, split-k: 64 dims each).
// T padded to 32x128 in smem (rows 27..31 zero). Z = T*T^T, but only the 6 of 8
// m16n8 output tiles that intersect the strict upper triangle are computed:
// (mt,nt) in {(0,0),(0,1),(0,2),(0,3),(1,2),(1,3)} — tiles (1,0),(1,1) lie
// entirely in i>j and were 100% discarded work in R8.

constexpr int Bt      = 16384;
constexpr int NE      = 26;
constexpr int D       = 128;
constexpr int N       = 27;
constexpr int NPAIR   = N * (N - 1) / 2;   // 351
constexpr int NROWS   = 32;                // padded for m16 tiles
constexpr int STRIDEF = 132;               // floats per smem row (33 float4)
constexpr int NTHR    = 64;
constexpr int NTILE   = 6;

__device__ __forceinline__ void mma_tf32(float* c, const uint32_t* a, const uint32_t* b)
{
    asm volatile(
        "mma.sync.aligned.m16n8k8.row.col.f32.tf32.tf32.f32 "
        "{%0,%1,%2,%3}, {%4,%5,%6,%7}, {%8,%9}, {%0,%1,%2,%3};"
        : "+f"(c[0]), "+f"(c[1]), "+f"(c[2]), "+f"(c[3])
        : "r"(a[0]), "r"(a[1]), "r"(a[2]), "r"(a[3]), "r"(b[0]), "r"(b[1]));
}

__device__ __forceinline__ void split_tf32(float x, uint32_t& hi, uint32_t& lo)
{
    uint32_t h = __float_as_uint(x) & 0xFFFFE000u;   // top 10 explicit mantissa bits
    hi = h;
    lo = __float_as_uint(x - __uint_as_float(h));    // exact residual in fp32
}

__global__ void __launch_bounds__(NTHR)
dot_interaction_kernel(const float* __restrict__ dense,
                       const float* __restrict__ embs,
                       float* __restrict__ out)
{
    __shared__ float S[NROWS * STRIDEF];             // 16896 B

    const int tid  = threadIdx.x;
    const int kw   = tid >> 5;                       // k-half: 0 or 1
    const int lane = tid & 31;
    const int g    = lane >> 2;                      // groupID
    const int t4   = lane & 3;                       // thread-in-group
    const int sample = blockIdx.x;

    // ---- Load phase: 64 threads stage T (32x128, rows 27..31 zero) ----
    float4* S4 = reinterpret_cast<float4*>(S);
    const float4* d4 = reinterpret_cast<const float4*>(dense + (size_t)sample * D);
    const float4* e4 = reinterpret_cast<const float4*>(embs + (size_t)sample * NE * D);

    if (tid < 32) S4[tid] = d4[tid];                 // row 0 = dense (32 float4)
    #pragma unroll
    for (int i = tid; i < NE * 32; i += NTHR) {      // rows 1..26 = embs (832 f4)
        const int row = i >> 5, col = i & 31;
        S4[(row + 1) * 33 + col] = e4[i];
    }
    #pragma unroll
    for (int i = tid; i < 5 * 33; i += NTHR)         // rows 27..31 = zero (165 f4)
        S4[27 * 33 + i] = make_float4(0.f, 0.f, 0.f, 0.f);
    __syncthreads();

    // ---- Compute: this warp covers k dims [kw*64, kw*64+64) = 8 ktiles ----
    // Upper-triangle tile list: e -> (mt, nt)
    constexpr int MT[NTILE] = {0, 0, 0, 0, 1, 1};
    constexpr int NT[NTILE] = {0, 1, 2, 3, 2, 3};

    float acc[NTILE][4];
    #pragma unroll
    for (int e = 0; e < NTILE; e++)
        #pragma unroll
        for (int c = 0; c < 4; c++) acc[e][c] = 0.f;

    const int kbase = kw * 64;

    #pragma unroll
    for (int kt = 0; kt < 8; kt++) {
        const int k0 = kbase + kt * 8;

        // A fragments (row-major 16x8): rows mt*16+g / +8, cols k0+t4 / +4
        uint32_t ah[2][4], al[2][4];
        #pragma unroll
        for (int mt = 0; mt < 2; mt++) {
            const int m0 = mt * 16 + g;
            split_tf32(S[ m0      * STRIDEF + k0 + t4    ], ah[mt][0], al[mt][0]);
            split_tf32(S[(m0 + 8) * STRIDEF + k0 + t4    ], ah[mt][1], al[mt][1]);
            split_tf32(S[ m0      * STRIDEF + k0 + t4 + 4], ah[mt][2], al[mt][2]);
            split_tf32(S[(m0 + 8) * STRIDEF + k0 + t4 + 4], ah[mt][3], al[mt][3]);
        }
        // B fragments (col-major 8k x 8n): B[k][n] = T[n][k]
        uint32_t bh[4][2], bl[4][2];
        #pragma unroll
        for (int nt = 0; nt < 4; nt++) {
            const int n = nt * 8 + g;
            split_tf32(S[n * STRIDEF + k0 + t4    ], bh[nt][0], bl[nt][0]);
            split_tf32(S[n * STRIDEF + k0 + t4 + 4], bh[nt][1], bl[nt][1]);
        }
        // 3xTF32 on the 6 useful tiles: small terms first, then hi*hi
        #pragma unroll
        for (int e = 0; e < NTILE; e++) {
            float* c = acc[e];
            mma_tf32(c, al[MT[e]], bh[NT[e]]);
            mma_tf32(c, ah[MT[e]], bl[NT[e]]);
            mma_tf32(c, ah[MT[e]], bh[NT[e]]);
        }
    }

    // ---- Cross-warp reduction via dead tile smem (3 KB at base of S) ----
    __syncthreads();                                 // everyone done reading T
    if (kw == 1) {
        #pragma unroll
        for (int e = 0; e < NTILE; e++)
            #pragma unroll
            for (int c = 0; c < 4; c++)
                S[(e * 4 + c) * 32 + lane] = acc[e][c];
    }
    __syncthreads();

    // ---- Epilogue: warp 0 adds partner partials, scatters strict-upper triu ----
    if (kw == 0) {
        float* orow = out + (size_t)sample * NPAIR;
        #pragma unroll
        for (int e = 0; e < NTILE; e++)
            #pragma unroll
            for (int c = 0; c < 4; c++) {
                const float v = acc[e][c] + S[(e * 4 + c) * 32 + lane];
                const int i = MT[e] * 16 + g + ((c & 2) ? 8 : 0);
                const int j = NT[e] * 8 + 2 * t4 + (c & 1);
                if (i < j && j < N)
                    orow[i * (2 * N - 1 - i) / 2 + (j - i - 1)] = v;
            }
    }
}

extern "C" void kernel_launch(void* const* d_in, const int* in_sizes, int n_in,
                              void* d_out, int out_size)
{
    const float* dense = (const float*)d_in[0];
    const float* embs  = (const float*)d_in[1];
    float* out = (float*)d_out;
    dot_interaction_kernel<<<Bt, NTHR>>>(dense, embs, out);
}

// round 10
// speedup vs baseline: 8.5295x; 1.2030x over previous
#include <cuda_runtime.h>
#include <cuda_bf16.h>
#include <cstdint>

// DLRM dot-interaction via BF16 tensor cores with 3-term split (fp32-grade accuracy).
// One sample per 64-thread CTA (2 warps, split-k: 64 dims each).
// T padded to 32x128 in smem (rows 27..31 zero), row stride 136 floats so the
// m16n8k16 fragment loads (addr ~ 4g+t4 mod 16) are bank-conflict-free.
// Only the 6 of 8 m16n8 output tiles intersecting the strict upper triangle are
// computed. Each pair position uses 3 bf16 mmas: ah*bh + ah*bl + al*bh, where
// x = x_hi(bf16 trunc) + x_lo(residual, rn-bf16); dropped al*bl ~ 2^-16.

constexpr int Bt      = 16384;
constexpr int NE      = 26;
constexpr int D       = 128;
constexpr int N       = 27;
constexpr int NPAIR   = N * (N - 1) / 2;   // 351
constexpr int STRF    = 136;               // floats per smem row
constexpr int STR4    = 34;                // float4 per smem row
constexpr int NTHR    = 64;
constexpr int NTILE   = 6;

__device__ __forceinline__ void mma_bf16(float* c, const uint32_t* a, const uint32_t* b)
{
    asm volatile(
        "mma.sync.aligned.m16n8k16.row.col.f32.bf16.bf16.f32 "
        "{%0,%1,%2,%3}, {%4,%5,%6,%7}, {%8,%9}, {%0,%1,%2,%3};"
        : "+f"(c[0]), "+f"(c[1]), "+f"(c[2]), "+f"(c[3])
        : "r"(a[0]), "r"(a[1]), "r"(a[2]), "r"(a[3]), "r"(b[0]), "r"(b[1]));
}

// Split a float2 into packed bf16 (hi, lo) pairs. hi = truncate-to-bf16 (exact
// top 16 bits, packed with one PRMT); lo = rn-bf16 of the exact fp32 residual.
__device__ __forceinline__ void split2(float2 v, uint32_t& hi, uint32_t& lo)
{
    const uint32_t bx = __float_as_uint(v.x), by = __float_as_uint(v.y);
    hi = __byte_perm(bx, by, 0x7632);        // low16 = v.x_hi, high16 = v.y_hi
    const float lx = v.x - __uint_as_float(bx & 0xFFFF0000u);
    const float ly = v.y - __uint_as_float(by & 0xFFFF0000u);
    __nv_bfloat162 l2 = __floats2bfloat162_rn(lx, ly);   // low = lx
    lo = *reinterpret_cast<uint32_t*>(&l2);
}

__global__ void __launch_bounds__(NTHR)
dot_interaction_kernel(const float* __restrict__ dense,
                       const float* __restrict__ embs,
                       float* __restrict__ out)
{
    __shared__ float S[32 * STRF];                   // 17408 B

    const int tid  = threadIdx.x;
    const int kw   = tid >> 5;                       // k-half: 0 or 1
    const int lane = tid & 31;
    const int g    = lane >> 2;                      // groupID
    const int t4   = lane & 3;                       // thread-in-group
    const int sample = blockIdx.x;

    // ---- Load phase: 64 threads stage T (32x128, rows 27..31 zero) ----
    float4* S4 = reinterpret_cast<float4*>(S);
    const float4* d4 = reinterpret_cast<const float4*>(dense + (size_t)sample * D);
    const float4* e4 = reinterpret_cast<const float4*>(embs + (size_t)sample * NE * D);

    if (tid < 32) S4[tid] = d4[tid];                 // row 0 = dense (32 float4)
    #pragma unroll
    for (int i = tid; i < NE * 32; i += NTHR) {      // rows 1..26 = embs (832 f4)
        const int row = i >> 5, col = i & 31;
        S4[(row + 1) * STR4 + col] = e4[i];
    }
    #pragma unroll
    for (int i = tid; i < 5 * STR4; i += NTHR)       // rows 27..31 = zero
        S4[27 * STR4 + i] = make_float4(0.f, 0.f, 0.f, 0.f);
    __syncthreads();

    // Upper-triangle tile list: e -> (mt, nt)
    constexpr int MT[NTILE] = {0, 0, 0, 0, 1, 1};
    constexpr int NT[NTILE] = {0, 1, 2, 3, 2, 3};

    float acc[NTILE][4];
    #pragma unroll
    for (int e = 0; e < NTILE; e++)
        #pragma unroll
        for (int c = 0; c < 4; c++) acc[e][c] = 0.f;

    const int kbase = kw * 64;                       // this warp's k-half

    #pragma unroll
    for (int kt = 0; kt < 4; kt++) {                 // 4 ktiles of k=16
        const int k0 = kbase + kt * 16;
        const int kc = k0 + 2 * t4;                  // this thread's col pair

        // A fragments (row-major 16x16): regs = (g,kc),(g+8,kc),(g,kc+8),(g+8,kc+8)
        uint32_t ah[2][4], al[2][4];
        #pragma unroll
        for (int mt = 0; mt < 2; mt++) {
            const int m0 = mt * 16 + g;
            split2(*reinterpret_cast<const float2*>(&S[ m0      * STRF + kc    ]), ah[mt][0], al[mt][0]);
            split2(*reinterpret_cast<const float2*>(&S[(m0 + 8) * STRF + kc    ]), ah[mt][1], al[mt][1]);
            split2(*reinterpret_cast<const float2*>(&S[ m0      * STRF + kc + 8]), ah[mt][2], al[mt][2]);
            split2(*reinterpret_cast<const float2*>(&S[(m0 + 8) * STRF + kc + 8]), ah[mt][3], al[mt][3]);
        }
        // B fragments (col-major 16k x 8n): B[k][n] = T[n][k]
        uint32_t bh[4][2], bl[4][2];
        #pragma unroll
        for (int nt = 0; nt < 4; nt++) {
            const int n = nt * 8 + g;
            split2(*reinterpret_cast<const float2*>(&S[n * STRF + kc    ]), bh[nt][0], bl[nt][0]);
            split2(*reinterpret_cast<const float2*>(&S[n * STRF + kc + 8]), bh[nt][1], bl[nt][1]);
        }
        // 3-term bf16 on the 6 useful tiles: small terms first, then hi*hi
        #pragma unroll
        for (int e = 0; e < NTILE; e++) {
            float* c = acc[e];
            mma_bf16(c, al[MT[e]], bh[NT[e]]);
            mma_bf16(c, ah[MT[e]], bl[NT[e]]);
            mma_bf16(c, ah[MT[e]], bh[NT[e]]);
        }
    }

    // ---- Cross-warp reduction via dead tile smem ----
    __syncthreads();                                 // everyone done reading T
    if (kw == 1) {
        #pragma unroll
        for (int e = 0; e < NTILE; e++)
            #pragma unroll
            for (int c = 0; c < 4; c++)
                S[(e * 4 + c) * 32 + lane] = acc[e][c];
    }
    __syncthreads();

    // ---- Epilogue: warp 0 adds partner partials, scatters strict-upper triu ----
    if (kw == 0) {
        float* orow = out + (size_t)sample * NPAIR;
        #pragma unroll
        for (int e = 0; e < NTILE; e++)
            #pragma unroll
            for (int c = 0; c < 4; c++) {
                const float v = acc[e][c] + S[(e * 4 + c) * 32 + lane];
                const int i = MT[e] * 16 + g + ((c & 2) ? 8 : 0);
                const int j = NT[e] * 8 + 2 * t4 + (c & 1);
                if (i < j && j < N)
                    orow[i * (2 * N - 1 - i) / 2 + (j - i - 1)] = v;
            }
    }
}

extern "C" void kernel_launch(void* const* d_in, const int* in_sizes, int n_in,
                              void* d_out, int out_size)
{
    const float* dense = (const float*)d_in[0];
    const float* embs  = (const float*)d_in[1];
    float* out = (float*)d_out;
    dot_interaction_kernel<<<Bt, NTHR>>>(dense, embs, out);
}